// round 13
// baseline (speedup 1.0000x reference)
#include <cuda_runtime.h>
#include <cuda_bf16.h>
#include <cstdint>
#include <math.h>

#define NDIM 256
#define IMG (NDIM * NDIM)
#define NIMG (128 * 3)
#define BM 128
#define BN 128
#define BK 32
#define SA 40    // A smem row stride (bf16): 80B = 5*16B odd -> conflict-free ldmatrix
#define SBN 136  // B smem row stride (bf16): 272B = 17*16B odd -> conflict-free

#define A_BYTES (BM * SA * 2)                  // 10240
#define B_BYTES (BK * SBN * 2)                 // 8704
#define BUF_BYTES (2 * A_BYTES + 2 * B_BYTES)  // 37888
#define NBUF 3
#define SMEM_BYTES (NBUF * BUF_BYTES)          // 113664

// ---- device globals (no allocation allowed) ----
__device__ __nv_bfloat16 g_Ch[IMG], g_Cl[IMG];
__device__ __nv_bfloat16 g_CTh[IMG], g_CTl[IMG];
__device__ __nv_bfloat16 g_t1h[NIMG * IMG], g_t1l[NIMG * IMG];
__device__ __nv_bfloat16 g_t2h[NIMG * IMG], g_t2l[NIMG * IMG];

// DCT-II orthonormal matrix, pre-split into bf16 hi/lo, plus transpose.
__global__ void init_C_kernel() {
    int idx = blockIdx.x * blockDim.x + threadIdx.x;
    if (idx >= IMG) return;
    int k = idx >> 8, n = idx & 255;
    double v = cos(M_PI * ((double)n + 0.5) * (double)k / (double)NDIM);
    double s = (k == 0) ? sqrt(1.0 / NDIM) : sqrt(2.0 / NDIM);
    float f = (float)(v * s);
    __nv_bfloat16 h = __float2bfloat16_rn(f);
    __nv_bfloat16 l = __float2bfloat16_rn(f - __bfloat162float(h));
    g_Ch[k * NDIM + n] = h;
    g_Cl[k * NDIM + n] = l;
    g_CTh[n * NDIM + k] = h;
    g_CTl[n * NDIM + k] = l;
}

// Pre-split X (fp32) into bf16 hi/lo pairs stored in g_t2 (free at stage 0).
__global__ void split_x_kernel(const float* __restrict__ x) {
    size_t i = ((size_t)blockIdx.x * 256 + threadIdx.x) * 4;
    float4 v = *reinterpret_cast<const float4*>(x + i);
    __nv_bfloat162 h0, h1, l0, l1;
    h0.x = __float2bfloat16_rn(v.x); h0.y = __float2bfloat16_rn(v.y);
    h1.x = __float2bfloat16_rn(v.z); h1.y = __float2bfloat16_rn(v.w);
    l0.x = __float2bfloat16_rn(v.x - __bfloat162float(h0.x));
    l0.y = __float2bfloat16_rn(v.y - __bfloat162float(h0.y));
    l1.x = __float2bfloat16_rn(v.z - __bfloat162float(h1.x));
    l1.y = __float2bfloat16_rn(v.w - __bfloat162float(h1.y));
    *reinterpret_cast<__nv_bfloat162*>(g_t2h + i) = h0;
    *reinterpret_cast<__nv_bfloat162*>(g_t2h + i + 2) = h1;
    *reinterpret_cast<__nv_bfloat162*>(g_t2l + i) = l0;
    *reinterpret_cast<__nv_bfloat162*>(g_t2l + i + 2) = l1;
}

__device__ __forceinline__ uint32_t smem_u32(const void* p) {
    return (uint32_t)__cvta_generic_to_shared(p);
}
__device__ __forceinline__ void cpa16(uint32_t s, const void* g) {
    asm volatile("cp.async.cg.shared.global [%0], [%1], 16;" :: "r"(s), "l"(g));
}
__device__ __forceinline__ void ldsm4(uint32_t* r, uint32_t addr) {
    asm volatile("ldmatrix.sync.aligned.m8n8.x4.shared.b16 {%0,%1,%2,%3}, [%4];"
                 : "=r"(r[0]), "=r"(r[1]), "=r"(r[2]), "=r"(r[3]) : "r"(addr));
}
__device__ __forceinline__ void ldsm4t(uint32_t* r, uint32_t addr) {
    asm volatile("ldmatrix.sync.aligned.m8n8.x4.trans.shared.b16 {%0,%1,%2,%3}, [%4];"
                 : "=r"(r[0]), "=r"(r[1]), "=r"(r[2]), "=r"(r[3]) : "r"(addr));
}
__device__ __forceinline__ void mma16816(float* d, const uint32_t* a, const uint32_t* b) {
    asm volatile(
        "mma.sync.aligned.m16n8k16.row.col.f32.bf16.bf16.f32 "
        "{%0,%1,%2,%3}, {%4,%5,%6,%7}, {%8,%9}, {%0,%1,%2,%3};"
        : "+f"(d[0]), "+f"(d[1]), "+f"(d[2]), "+f"(d[3])
        : "r"(a[0]), "r"(a[1]), "r"(a[2]), "r"(a[3]), "r"(b[0]), "r"(b[1]));
}
__device__ __forceinline__ void split_store_pair(__nv_bfloat16* baseH, __nv_bfloat16* baseL,
                                                 size_t off, float v0, float v1) {
    __nv_bfloat16 h0 = __float2bfloat16_rn(v0);
    __nv_bfloat16 h1 = __float2bfloat16_rn(v1);
    __nv_bfloat162 hp; hp.x = h0; hp.y = h1;
    __nv_bfloat162 lp;
    lp.x = __float2bfloat16_rn(v0 - __bfloat162float(h0));
    lp.y = __float2bfloat16_rn(v1 - __bfloat162float(h1));
    *reinterpret_cast<__nv_bfloat162*>(baseH + off) = hp;
    *reinterpret_cast<__nv_bfloat162*>(baseL + off) = lp;
}

// Frequency cutoff: entries (k,n) with fade >= 0.01 require k,n < Km.
// Km = (256/pi)*sqrt(2 ln 100)/sigma = 247.31/sigma (+2 conservative margin).
// Identical fp sequence in all stages -> identical Km everywhere.
__device__ __forceinline__ int compute_Km(float tb) {
    float sig = expf(fmaf(tb, 3.6888794541139363f, -0.6931471805599453f));
    int km = (int)(247.32f / sig) + 2;
    return km > NDIM ? NDIM : km;
}

// Batched Out = A*B per image (256^3), bf16 hi/lo 3-term split.
// 3-buffer cp.async pipeline: ONE __syncthreads per slab; next slab's fill is
// issued before compute so LDG latency hides under the 96 MMAs.
// Exact frequency sparsity: out = 0.001*X + 0.999*C^T(fadeT . dct)C, fadeT zero
// outside [0,Km)^2 -> tile skips + truncated K-loops (all exact).
// MODE 0: T1 = C  * X     A: g_C      B: g_t2 (X presplit) -> g_t1  [rows < Km]
// MODE 1: Y  = T1 * C^T   A: g_t1     B: g_CT              -> g_t2  [tiles < Km; mask 0.999*fadeT]
// MODE 2: T2 = C^T* Y     A: g_CT     B: g_t2              -> g_t1  [cols < Km; K < Km32]
// MODE 3: out= T2 * C     A: g_t1     B: g_C               -> out   [K < Km32; +0.001*X]
template <int MODE>
__global__ void __launch_bounds__(256, 2) dct_mma(const float* __restrict__ xin,
                                                  float* __restrict__ gout,
                                                  const float* __restrict__ tarr) {
    extern __shared__ __align__(16) unsigned char smem[];

    const int img = blockIdx.z;
    const int m0 = blockIdx.y * BM;
    const int n0 = blockIdx.x * BN;

    const int Km = compute_Km(tarr[img / 3]);
    if constexpr (MODE == 0) { if (m0 >= Km) return; }
    if constexpr (MODE == 1) { if (m0 >= Km || n0 >= Km) return; }
    if constexpr (MODE == 2) { if (n0 >= Km) return; }
    int kend;
    if constexpr (MODE >= 2) {
        int km32 = (Km + 31) & ~31;
        kend = km32 > NDIM ? NDIM : km32;
    } else {
        kend = NDIM;
    }
    const int niter = kend / BK;

    const int tid = threadIdx.x;
    const int wid = tid >> 5;
    const int lane = tid & 31;
    const int wm = wid & 3;   // 4 warps along m (32 rows each)
    const int wn = wid >> 2;  // 2 warps along n (64 cols each)

    const __nv_bfloat16 *aH, *aL, *bH, *bL;
    if constexpr (MODE == 0)      { aH = g_Ch;  aL = g_Cl;
                                    bH = g_t2h + (size_t)img * IMG; bL = g_t2l + (size_t)img * IMG; }
    else if constexpr (MODE == 1) { aH = g_t1h + (size_t)img * IMG; aL = g_t1l + (size_t)img * IMG;
                                    bH = g_CTh; bL = g_CTl; }
    else if constexpr (MODE == 2) { aH = g_CTh; aL = g_CTl;
                                    bH = g_t2h + (size_t)img * IMG; bL = g_t2l + (size_t)img * IMG; }
    else                          { aH = g_t1h + (size_t)img * IMG; aL = g_t1l + (size_t)img * IMG;
                                    bH = g_Ch;  bL = g_Cl; }

    const uint32_t smem_base = smem_u32(smem);

    auto issue = [&](int k0, int b) {
        uint32_t base = smem_base + b * BUF_BYTES;
#pragma unroll
        for (int u = 0; u < 2; u++) {
            int idx = tid + 256 * u;
            int m = idx >> 2, k8 = (idx & 3) * 8;
            size_t goff = (size_t)(m0 + m) * NDIM + k0 + k8;
            uint32_t soff = (uint32_t)(m * SA + k8) * 2;
            cpa16(base + soff, aH + goff);
            cpa16(base + A_BYTES + soff, aL + goff);
        }
#pragma unroll
        for (int u = 0; u < 2; u++) {
            int idx = tid + 256 * u;
            int k = idx >> 4, n8 = (idx & 15) * 8;
            size_t goff = (size_t)(k0 + k) * NDIM + n0 + n8;
            uint32_t soff = (uint32_t)(k * SBN + n8) * 2;
            cpa16(base + 2 * A_BYTES + soff, bH + goff);
            cpa16(base + 2 * A_BYTES + B_BYTES + soff, bL + goff);
        }
    };

    float d[2][8][4];
#pragma unroll
    for (int i = 0; i < 2; i++)
#pragma unroll
        for (int j = 0; j < 8; j++)
#pragma unroll
            for (int q = 0; q < 4; q++) d[i][j][q] = 0.0f;

    issue(0, 0);
    asm volatile("cp.async.commit_group;" ::: "memory");
    issue(BK, 1);   // always in-bounds; unused when niter==1
    asm volatile("cp.async.commit_group;" ::: "memory");

    for (int it = 0; it < niter; it++) {
        asm volatile("cp.async.wait_group 1;" ::: "memory");
        __syncthreads();   // slab `it` visible to all; buf (it+2)%3 free (readers done at it-1)

        // overlap next fill with this slab's compute
        if (it + 2 < niter) issue((it + 2) * BK, (it + 2) % NBUF);
        asm volatile("cp.async.commit_group;" ::: "memory");

        const int b = it % NBUF;
        const uint32_t ahB = smem_base + b * BUF_BYTES;
        const uint32_t alB = ahB + A_BYTES;
        const uint32_t bhB = ahB + 2 * A_BYTES;
        const uint32_t blB = bhB + B_BYTES;

#pragma unroll
        for (int kk = 0; kk < BK; kk += 16) {
            uint32_t fAh[2][4], fAl[2][4];
#pragma unroll
            for (int mt = 0; mt < 2; mt++) {
                int row = wm * 32 + mt * 16 + (lane & 7) + ((lane >> 3) & 1) * 8;
                int col = kk + (lane >> 4) * 8;
                uint32_t off = (uint32_t)(row * SA + col) * 2;
                ldsm4(fAh[mt], ahB + off);
                ldsm4(fAl[mt], alB + off);
            }
#pragma unroll
            for (int nt2 = 0; nt2 < 4; nt2++) {
                int row = kk + (lane & 7) + ((lane >> 3) & 1) * 8;
                int col = wn * 64 + nt2 * 16 + (lane >> 4) * 8;
                uint32_t off = (uint32_t)(row * SBN + col) * 2;
                uint32_t rh[4], rl[4];
                ldsm4t(rh, bhB + off);
                ldsm4t(rl, blB + off);
#pragma unroll
                for (int mt = 0; mt < 2; mt++) {
                    mma16816(d[mt][nt2 * 2 + 0], fAh[mt], &rh[0]);
                    mma16816(d[mt][nt2 * 2 + 0], fAh[mt], &rl[0]);
                    mma16816(d[mt][nt2 * 2 + 0], fAl[mt], &rh[0]);
                    mma16816(d[mt][nt2 * 2 + 1], fAh[mt], &rh[2]);
                    mma16816(d[mt][nt2 * 2 + 1], fAh[mt], &rl[2]);
                    mma16816(d[mt][nt2 * 2 + 1], fAl[mt], &rh[2]);
                }
            }
        }
    }

    // ---- epilogue ----
    const int g = lane >> 2, q = lane & 3;

    if constexpr (MODE == 1) {
        // mask = 0.999 * fadeT (threshold-exact; 0.001 floor handled in MODE 3)
        const float PI_N = 0.01227184630308513f;  // pi/256
        float tb = tarr[img / 3];
        float sig = expf(fmaf(tb, 3.6888794541139363f, -0.6931471805599453f));
        float tau = 0.5f * sig * sig;
        float rf[2][2], cf[8][2];
#pragma unroll
        for (int mt = 0; mt < 2; mt++) {
            int r0 = m0 + wm * 32 + mt * 16 + g;
            float f0 = (float)r0 * PI_N, f1 = (float)(r0 + 8) * PI_N;
            rf[mt][0] = expf(-f0 * f0 * tau);
            rf[mt][1] = expf(-f1 * f1 * tau);
        }
#pragma unroll
        for (int nt = 0; nt < 8; nt++) {
            int c0 = n0 + wn * 64 + nt * 8 + q * 2;
            float f0 = (float)c0 * PI_N, f1 = (float)(c0 + 1) * PI_N;
            cf[nt][0] = expf(-f0 * f0 * tau);
            cf[nt][1] = expf(-f1 * f1 * tau);
        }
        __nv_bfloat16* oH = g_t2h + (size_t)img * IMG;
        __nv_bfloat16* oL = g_t2l + (size_t)img * IMG;
#pragma unroll
        for (int mt = 0; mt < 2; mt++)
#pragma unroll
            for (int nt = 0; nt < 8; nt++) {
                int r0 = m0 + wm * 32 + mt * 16 + g;
                int c0 = n0 + wn * 64 + nt * 8 + q * 2;
#pragma unroll
                for (int rh = 0; rh < 2; rh++) {
                    float fa0 = rf[mt][rh] * cf[nt][0];
                    float fa1 = rf[mt][rh] * cf[nt][1];
                    if (fa0 < 0.01f) fa0 = 0.0f;
                    if (fa1 < 0.01f) fa1 = 0.0f;
                    float v0 = d[mt][nt][rh * 2 + 0] * (0.999f * fa0);
                    float v1 = d[mt][nt][rh * 2 + 1] * (0.999f * fa1);
                    split_store_pair(oH, oL, (size_t)(r0 + rh * 8) * NDIM + c0, v0, v1);
                }
            }
    } else if constexpr (MODE == 3) {
        float* outImg = gout + (size_t)img * IMG;
        const float* xim = xin + (size_t)img * IMG;
#pragma unroll
        for (int mt = 0; mt < 2; mt++)
#pragma unroll
            for (int nt = 0; nt < 8; nt++) {
                int r0 = m0 + wm * 32 + mt * 16 + g;
                int c0 = n0 + wn * 64 + nt * 8 + q * 2;
#pragma unroll
                for (int rh = 0; rh < 2; rh++) {
                    size_t off = (size_t)(r0 + rh * 8) * NDIM + c0;
                    float2 xv = *reinterpret_cast<const float2*>(&xim[off]);
                    float2 o = make_float2(fmaf(0.001f, xv.x, d[mt][nt][rh * 2 + 0]),
                                           fmaf(0.001f, xv.y, d[mt][nt][rh * 2 + 1]));
                    *reinterpret_cast<float2*>(&outImg[off]) = o;
                }
            }
    } else {
        __nv_bfloat16* oH = g_t1h + (size_t)img * IMG;
        __nv_bfloat16* oL = g_t1l + (size_t)img * IMG;
#pragma unroll
        for (int mt = 0; mt < 2; mt++)
#pragma unroll
            for (int nt = 0; nt < 8; nt++) {
                int r0 = m0 + wm * 32 + mt * 16 + g;
                int c0 = n0 + wn * 64 + nt * 8 + q * 2;
#pragma unroll
                for (int rh = 0; rh < 2; rh++) {
                    split_store_pair(oH, oL, (size_t)(r0 + rh * 8) * NDIM + c0,
                                     d[mt][nt][rh * 2 + 0], d[mt][nt][rh * 2 + 1]);
                }
            }
    }
}

extern "C" void kernel_launch(void* const* d_in, const int* in_sizes, int n_in,
                              void* d_out, int out_size) {
    const float* x = (const float*)d_in[0];   // (128,3,256,256) fp32
    const float* t = (const float*)d_in[1];   // (128,) fp32
    float* out = (float*)d_out;               // (128,3,256,256) fp32

    cudaFuncSetAttribute(dct_mma<0>, cudaFuncAttributeMaxDynamicSharedMemorySize, SMEM_BYTES);
    cudaFuncSetAttribute(dct_mma<1>, cudaFuncAttributeMaxDynamicSharedMemorySize, SMEM_BYTES);
    cudaFuncSetAttribute(dct_mma<2>, cudaFuncAttributeMaxDynamicSharedMemorySize, SMEM_BYTES);
    cudaFuncSetAttribute(dct_mma<3>, cudaFuncAttributeMaxDynamicSharedMemorySize, SMEM_BYTES);

    init_C_kernel<<<(IMG + 255) / 256, 256>>>();
    split_x_kernel<<<(NIMG * IMG) / (256 * 4), 256>>>(x);

    dim3 blk(256, 1, 1);
    dim3 grd(NDIM / BN, NDIM / BM, NIMG);  // (2, 2, 384)
    dct_mma<0><<<grd, blk, SMEM_BYTES>>>(x, nullptr, t);
    dct_mma<1><<<grd, blk, SMEM_BYTES>>>(x, nullptr, t);
    dct_mma<2><<<grd, blk, SMEM_BYTES>>>(x, nullptr, t);
    dct_mma<3><<<grd, blk, SMEM_BYTES>>>(x, out, t);
}

// round 15
// speedup vs baseline: 1.0347x; 1.0347x over previous
#include <cuda_runtime.h>
#include <cuda_bf16.h>
#include <cstdint>
#include <math.h>

#define NDIM 256
#define IMG (NDIM * NDIM)
#define NIMG (128 * 3)
#define BM 128
#define BN 64
#define BK 32
#define SA 40   // A smem row stride (bf16): 80B = 5*16B odd -> conflict-free ldmatrix
#define SB 72   // B smem row stride (bf16): 144B = 9*16B odd -> conflict-free

#define A_BYTES (BM * SA * 2)                  // 10240
#define B_BYTES (BK * SB * 2)                  // 4608
#define BUF_BYTES (2 * A_BYTES + 2 * B_BYTES)  // 29696
#define SMEM_BYTES (2 * BUF_BYTES)             // 59392

// ---- device globals (no allocation allowed) ----
__device__ __nv_bfloat16 g_Ch[IMG], g_Cl[IMG];
__device__ __nv_bfloat16 g_CTh[IMG], g_CTl[IMG];
__device__ __nv_bfloat16 g_t1h[NIMG * IMG], g_t1l[NIMG * IMG];
__device__ __nv_bfloat16 g_t2h[NIMG * IMG], g_t2l[NIMG * IMG];

// DCT-II orthonormal matrix, pre-split into bf16 hi/lo, plus transpose.
__global__ void init_C_kernel() {
    int idx = blockIdx.x * blockDim.x + threadIdx.x;
    if (idx >= IMG) return;
    int k = idx >> 8, n = idx & 255;
    double v = cos(M_PI * ((double)n + 0.5) * (double)k / (double)NDIM);
    double s = (k == 0) ? sqrt(1.0 / NDIM) : sqrt(2.0 / NDIM);
    float f = (float)(v * s);
    __nv_bfloat16 h = __float2bfloat16_rn(f);
    __nv_bfloat16 l = __float2bfloat16_rn(f - __bfloat162float(h));
    g_Ch[k * NDIM + n] = h;
    g_Cl[k * NDIM + n] = l;
    g_CTh[n * NDIM + k] = h;
    g_CTl[n * NDIM + k] = l;
}

// Pre-split X (fp32) into bf16 hi/lo pairs stored in g_t2 (re-run every launch
// -> restores X over Y from the previous replay).
__global__ void split_x_kernel(const float* __restrict__ x) {
    size_t i = ((size_t)blockIdx.x * 256 + threadIdx.x) * 4;
    float4 v = *reinterpret_cast<const float4*>(x + i);
    __nv_bfloat162 h0, h1, l0, l1;
    h0.x = __float2bfloat16_rn(v.x); h0.y = __float2bfloat16_rn(v.y);
    h1.x = __float2bfloat16_rn(v.z); h1.y = __float2bfloat16_rn(v.w);
    l0.x = __float2bfloat16_rn(v.x - __bfloat162float(h0.x));
    l0.y = __float2bfloat16_rn(v.y - __bfloat162float(h0.y));
    l1.x = __float2bfloat16_rn(v.z - __bfloat162float(h1.x));
    l1.y = __float2bfloat16_rn(v.w - __bfloat162float(h1.y));
    *reinterpret_cast<__nv_bfloat162*>(g_t2h + i) = h0;
    *reinterpret_cast<__nv_bfloat162*>(g_t2h + i + 2) = h1;
    *reinterpret_cast<__nv_bfloat162*>(g_t2l + i) = l0;
    *reinterpret_cast<__nv_bfloat162*>(g_t2l + i + 2) = l1;
}

__device__ __forceinline__ uint32_t smem_u32(const void* p) {
    return (uint32_t)__cvta_generic_to_shared(p);
}
__device__ __forceinline__ void cpa16(uint32_t s, const void* g) {
    asm volatile("cp.async.cg.shared.global [%0], [%1], 16;" :: "r"(s), "l"(g));
}
__device__ __forceinline__ void ldsm4(uint32_t* r, uint32_t addr) {
    asm volatile("ldmatrix.sync.aligned.m8n8.x4.shared.b16 {%0,%1,%2,%3}, [%4];"
                 : "=r"(r[0]), "=r"(r[1]), "=r"(r[2]), "=r"(r[3]) : "r"(addr));
}
__device__ __forceinline__ void ldsm4t(uint32_t* r, uint32_t addr) {
    asm volatile("ldmatrix.sync.aligned.m8n8.x4.trans.shared.b16 {%0,%1,%2,%3}, [%4];"
                 : "=r"(r[0]), "=r"(r[1]), "=r"(r[2]), "=r"(r[3]) : "r"(addr));
}
__device__ __forceinline__ void mma16816(float* d, const uint32_t* a, const uint32_t* b) {
    asm volatile(
        "mma.sync.aligned.m16n8k16.row.col.f32.bf16.bf16.f32 "
        "{%0,%1,%2,%3}, {%4,%5,%6,%7}, {%8,%9}, {%0,%1,%2,%3};"
        : "+f"(d[0]), "+f"(d[1]), "+f"(d[2]), "+f"(d[3])
        : "r"(a[0]), "r"(a[1]), "r"(a[2]), "r"(a[3]), "r"(b[0]), "r"(b[1]));
}
__device__ __forceinline__ void split_store_pair(__nv_bfloat16* baseH, __nv_bfloat16* baseL,
                                                 size_t off, float v0, float v1) {
    __nv_bfloat16 h0 = __float2bfloat16_rn(v0);
    __nv_bfloat16 h1 = __float2bfloat16_rn(v1);
    __nv_bfloat162 hp; hp.x = h0; hp.y = h1;
    __nv_bfloat162 lp;
    lp.x = __float2bfloat16_rn(v0 - __bfloat162float(h0));
    lp.y = __float2bfloat16_rn(v1 - __bfloat162float(h1));
    *reinterpret_cast<__nv_bfloat162*>(baseH + off) = hp;
    *reinterpret_cast<__nv_bfloat162*>(baseL + off) = lp;
}

// sigma, and cutoffs. fade(r)=exp(-(PI_N*r)^2*tau) < 0.01 iff r > Rstar = 247.31/sigma.
// Km = int(Rstar)+2 (capped 256): 1D skip bound, >= Rstar+1 margin.
// Rf = Rstar+2 (uncapped): circular bound; radius >= Rf => entry exactly zero.
__device__ __forceinline__ float compute_sig(float tb) {
    return expf(fmaf(tb, 3.6888794541139363f, -0.6931471805599453f));
}
__device__ __forceinline__ int km_of(float sig) {
    int km = (int)(247.32f / sig) + 2;
    return km > NDIM ? NDIM : km;
}

// Batched Out = A*B per image (256^3), bf16 hi/lo 3-term split, cp.async 2-buf.
// Exact sparsity: out = 0.001*X + 0.999*C^T(fadeT . dct)C; fadeT zero outside
// radius Rstar. Tile skips (1D + circular), truncated/circular K. All exact.
// MODE 0: T1 = C  * X     A: g_C    B: g_t2(X)  -> g_t1  [m0 < Km]
// MODE 1: Y  = T1 * C^T   A: g_t1   B: g_CT     -> g_t2  [m0,n0 < Km; circle-skip
//                                                          tiles zero-filled; mask 0.999*fadeT]
// MODE 2: T2 = C^T* Y     A: g_CT   B: g_t2     -> g_t1  [n0 < Km; K < circ(n0)]
// MODE 3: out= T2 * C     A: g_t1   B: g_C      -> out   [K < Km32; +0.001*X]
template <int MODE>
__global__ void __launch_bounds__(256, 3) dct_mma(const float* __restrict__ xin,
                                                  float* __restrict__ gout,
                                                  const float* __restrict__ tarr) {
    extern __shared__ __align__(16) unsigned char smem[];

    const int img = blockIdx.z;
    const int m0 = blockIdx.y * BM;
    const int n0 = blockIdx.x * BN;
    const int tid = threadIdx.x;

    const float sig = compute_sig(tarr[img / 3]);
    const int Km = km_of(sig);
    const float Rf = 247.32f / sig + 2.0f;

    if constexpr (MODE == 0) { if (m0 >= Km) return; }
    if constexpr (MODE == 1) {
        if (m0 >= Km || n0 >= Km) return;  // 1D skip: never read by M2 (proven)
        if ((float)(m0 * m0 + n0 * n0) >= Rf * Rf) {
            // entire tile exactly zero: zero-fill Y (M2 reads it) and exit
            __nv_bfloat16* oH = g_t2h + (size_t)img * IMG;
            __nv_bfloat16* oL = g_t2l + (size_t)img * IMG;
            uint4 z = make_uint4(0, 0, 0, 0);
#pragma unroll
            for (int u = 0; u < 4; u++) {
                int idx = tid + 256 * u;          // 128*64/8 = 1024 uint4 per array
                int r = idx >> 3, c8 = (idx & 7) * 8;
                size_t off = (size_t)(m0 + r) * NDIM + n0 + c8;
                *reinterpret_cast<uint4*>(oH + off) = z;
                *reinterpret_cast<uint4*>(oL + off) = z;
            }
            return;
        }
    }
    if constexpr (MODE == 2) { if (n0 >= Km) return; }

    int kend;
    if constexpr (MODE == 2) {
        // circular K: Y rows k >= sqrt(Rf^2 - n0^2) are exactly zero for all
        // cols in this tile (min col = n0). Cap at ceil32(Km) (written region).
        int cap = (Km + 31) & ~31; if (cap > NDIM) cap = NDIM;
        float s2 = Rf * Rf - (float)(n0 * n0);
        int kb = (s2 > 0.0f) ? ((int)sqrtf(s2) + 1) : 1;
        kend = (kb + 31) & ~31;
        if (kend > cap) kend = cap;
    } else if constexpr (MODE == 3) {
        int cap = (Km + 31) & ~31; if (cap > NDIM) cap = NDIM;
        kend = cap;
    } else {
        kend = NDIM;
    }
    const int niter = kend / BK;

    const int wid = tid >> 5;
    const int lane = tid & 31;
    const int wm = wid & 3;   // 4 warps along m (32 rows each)
    const int wn = wid >> 2;  // 2 warps along n (32 cols each)

    const __nv_bfloat16 *aH, *aL, *bH, *bL;
    if constexpr (MODE == 0)      { aH = g_Ch;  aL = g_Cl;
                                    bH = g_t2h + (size_t)img * IMG; bL = g_t2l + (size_t)img * IMG; }
    else if constexpr (MODE == 1) { aH = g_t1h + (size_t)img * IMG; aL = g_t1l + (size_t)img * IMG;
                                    bH = g_CTh; bL = g_CTl; }
    else if constexpr (MODE == 2) { aH = g_CTh; aL = g_CTl;
                                    bH = g_t2h + (size_t)img * IMG; bL = g_t2l + (size_t)img * IMG; }
    else                          { aH = g_t1h + (size_t)img * IMG; aL = g_t1l + (size_t)img * IMG;
                                    bH = g_Ch;  bL = g_Cl; }

    const uint32_t smem_base = smem_u32(smem);

    auto issue = [&](int k0, int b) {
        uint32_t base = smem_base + b * BUF_BYTES;
#pragma unroll
        for (int u = 0; u < 2; u++) {           // A: 128x32 x2 arrays, 2 chunks/thread
            int idx = tid + 256 * u;
            int m = idx >> 2, k8 = (idx & 3) * 8;
            size_t goff = (size_t)(m0 + m) * NDIM + k0 + k8;
            uint32_t soff = (uint32_t)(m * SA + k8) * 2;
            cpa16(base + soff, aH + goff);
            cpa16(base + A_BYTES + soff, aL + goff);
        }
        {                                        // B: 32x64 x2 arrays, 1 chunk/thread
            int k = tid >> 3, n8 = (tid & 7) * 8;
            size_t goff = (size_t)(k0 + k) * NDIM + n0 + n8;
            uint32_t soff = (uint32_t)(k * SB + n8) * 2;
            cpa16(base + 2 * A_BYTES + soff, bH + goff);
            cpa16(base + 2 * A_BYTES + B_BYTES + soff, bL + goff);
        }
    };

    float d[2][4][4];
#pragma unroll
    for (int i = 0; i < 2; i++)
#pragma unroll
        for (int j = 0; j < 4; j++)
#pragma unroll
            for (int q = 0; q < 4; q++) d[i][j][q] = 0.0f;

    issue(0, 0);
    asm volatile("cp.async.commit_group;" ::: "memory");
    issue(BK, 1);   // always in-bounds; unused when niter==1
    asm volatile("cp.async.commit_group;" ::: "memory");

    for (int it = 0; it < niter; it++) {
        asm volatile("cp.async.wait_group 1;" ::: "memory");
        __syncthreads();

        const int b = it & 1;
        const uint32_t ahB = smem_base + b * BUF_BYTES;
        const uint32_t alB = ahB + A_BYTES;
        const uint32_t bhB = ahB + 2 * A_BYTES;
        const uint32_t blB = bhB + B_BYTES;

#pragma unroll
        for (int kk = 0; kk < BK; kk += 16) {
            uint32_t fAh[2][4], fAl[2][4];
#pragma unroll
            for (int mt = 0; mt < 2; mt++) {
                int row = wm * 32 + mt * 16 + (lane & 7) + ((lane >> 3) & 1) * 8;
                int col = kk + (lane >> 4) * 8;
                uint32_t off = (uint32_t)(row * SA + col) * 2;
                ldsm4(fAh[mt], ahB + off);
                ldsm4(fAl[mt], alB + off);
            }
#pragma unroll
            for (int nt2 = 0; nt2 < 2; nt2++) {
                int row = kk + (lane & 7) + ((lane >> 3) & 1) * 8;
                int col = wn * 32 + nt2 * 16 + (lane >> 4) * 8;
                uint32_t off = (uint32_t)(row * SB + col) * 2;
                uint32_t rh[4], rl[4];
                ldsm4t(rh, bhB + off);
                ldsm4t(rl, blB + off);
#pragma unroll
                for (int mt = 0; mt < 2; mt++) {
                    mma16816(d[mt][nt2 * 2 + 0], fAh[mt], &rh[0]);
                    mma16816(d[mt][nt2 * 2 + 0], fAh[mt], &rl[0]);
                    mma16816(d[mt][nt2 * 2 + 0], fAl[mt], &rh[0]);
                    mma16816(d[mt][nt2 * 2 + 1], fAh[mt], &rh[2]);
                    mma16816(d[mt][nt2 * 2 + 1], fAh[mt], &rl[2]);
                    mma16816(d[mt][nt2 * 2 + 1], fAl[mt], &rh[2]);
                }
            }
        }
        __syncthreads();
        if (it + 2 < niter) issue((it + 2) * BK, b);
        asm volatile("cp.async.commit_group;" ::: "memory");
    }

    // ---- epilogue ----
    const int g = lane >> 2, q = lane & 3;

    if constexpr (MODE == 1) {
        // mask = 0.999 * fadeT (threshold-exact; 0.001 floor handled in MODE 3)
        const float PI_N = 0.01227184630308513f;  // pi/256
        float tau = 0.5f * sig * sig;
        float rf[2][2], cf[4][2];
#pragma unroll
        for (int mt = 0; mt < 2; mt++) {
            int r0 = m0 + wm * 32 + mt * 16 + g;
            float f0 = (float)r0 * PI_N, f1 = (float)(r0 + 8) * PI_N;
            rf[mt][0] = expf(-f0 * f0 * tau);
            rf[mt][1] = expf(-f1 * f1 * tau);
        }
#pragma unroll
        for (int nt = 0; nt < 4; nt++) {
            int c0 = n0 + wn * 32 + nt * 8 + q * 2;
            float f0 = (float)c0 * PI_N, f1 = (float)(c0 + 1) * PI_N;
            cf[nt][0] = expf(-f0 * f0 * tau);
            cf[nt][1] = expf(-f1 * f1 * tau);
        }
        __nv_bfloat16* oH = g_t2h + (size_t)img * IMG;
        __nv_bfloat16* oL = g_t2l + (size_t)img * IMG;
#pragma unroll
        for (int mt = 0; mt < 2; mt++)
#pragma unroll
            for (int nt = 0; nt < 4; nt++) {
                int r0 = m0 + wm * 32 + mt * 16 + g;
                int c0 = n0 + wn * 32 + nt * 8 + q * 2;
#pragma unroll
                for (int rh = 0; rh < 2; rh++) {
                    float fa0 = rf[mt][rh] * cf[nt][0];
                    float fa1 = rf[mt][rh] * cf[nt][1];
                    if (fa0 < 0.01f) fa0 = 0.0f;
                    if (fa1 < 0.01f) fa1 = 0.0f;
                    float v0 = d[mt][nt][rh * 2 + 0] * (0.999f * fa0);
                    float v1 = d[mt][nt][rh * 2 + 1] * (0.999f * fa1);
                    split_store_pair(oH, oL, (size_t)(r0 + rh * 8) * NDIM + c0, v0, v1);
                }
            }
    } else if constexpr (MODE == 3) {
        float* outImg = gout + (size_t)img * IMG;
        const float* xim = xin + (size_t)img * IMG;
#pragma unroll
        for (int mt = 0; mt < 2; mt++)
#pragma unroll
            for (int nt = 0; nt < 4; nt++) {
                int r0 = m0 + wm * 32 + mt * 16 + g;
                int c0 = n0 + wn * 32 + nt * 8 + q * 2;
#pragma unroll
                for (int rh = 0; rh < 2; rh++) {
                    size_t off = (size_t)(r0 + rh * 8) * NDIM + c0;
                    float2 xv = *reinterpret_cast<const float2*>(&xim[off]);
                    float2 o = make_float2(fmaf(0.001f, xv.x, d[mt][nt][rh * 2 + 0]),
                                           fmaf(0.001f, xv.y, d[mt][nt][rh * 2 + 1]));
                    *reinterpret_cast<float2*>(&outImg[off]) = o;
                }
            }
    } else {
        __nv_bfloat16* oH = g_t1h + (size_t)img * IMG;
        __nv_bfloat16* oL = g_t1l + (size_t)img * IMG;
#pragma unroll
        for (int mt = 0; mt < 2; mt++)
#pragma unroll
            for (int nt = 0; nt < 4; nt++) {
                int r0 = m0 + wm * 32 + mt * 16 + g;
                int c0 = n0 + wn * 32 + nt * 8 + q * 2;
#pragma unroll
                for (int rh = 0; rh < 2; rh++) {
                    split_store_pair(oH, oL, (size_t)(r0 + rh * 8) * NDIM + c0,
                                     d[mt][nt][rh * 2 + 0], d[mt][nt][rh * 2 + 1]);
                }
            }
    }
}

extern "C" void kernel_launch(void* const* d_in, const int* in_sizes, int n_in,
                              void* d_out, int out_size) {
    const float* x = (const float*)d_in[0];   // (128,3,256,256) fp32
    const float* t = (const float*)d_in[1];   // (128,) fp32
    float* out = (float*)d_out;               // (128,3,256,256) fp32

    cudaFuncSetAttribute(dct_mma<0>, cudaFuncAttributeMaxDynamicSharedMemorySize, SMEM_BYTES);
    cudaFuncSetAttribute(dct_mma<1>, cudaFuncAttributeMaxDynamicSharedMemorySize, SMEM_BYTES);
    cudaFuncSetAttribute(dct_mma<2>, cudaFuncAttributeMaxDynamicSharedMemorySize, SMEM_BYTES);
    cudaFuncSetAttribute(dct_mma<3>, cudaFuncAttributeMaxDynamicSharedMemorySize, SMEM_BYTES);

    init_C_kernel<<<(IMG + 255) / 256, 256>>>();
    split_x_kernel<<<(NIMG * IMG) / (256 * 4), 256>>>(x);

    dim3 blk(256, 1, 1);
    dim3 grd(NDIM / BN, NDIM / BM, NIMG);  // (4, 2, 384)
    dct_mma<0><<<grd, blk, SMEM_BYTES>>>(x, nullptr, t);
    dct_mma<1><<<grd, blk, SMEM_BYTES>>>(x, nullptr, t);
    dct_mma<2><<<grd, blk, SMEM_BYTES>>>(x, nullptr, t);
    dct_mma<3><<<grd, blk, SMEM_BYTES>>>(x, out, t);
}